// round 10
// baseline (speedup 1.0000x reference)
#include <cuda_runtime.h>
#include <cuda_bf16.h>
#include <cstdint>

#define Bn 8192
#define Dn 256
#define INn 64
#define ONn 256

typedef unsigned int u32;
typedef unsigned short u16;
typedef unsigned char u8;

// A matrix (inner acts) as bf16 hi/lo, layout [d][b] (for ldmatrix.trans)
__device__ __align__(16) u16 g_Ah16[(size_t)Dn * Bn];   // 4MB
__device__ __align__(16) u16 g_Al16[(size_t)Dn * Bn];   // 4MB
__device__ float g_lutT[Dn * INn];
__device__ __align__(16) float2 g_lutSC[Dn * (INn + 1)];
__device__ __align__(16) u8 g_pst[Dn * 256];            // bucket -> start segment

__device__ __forceinline__ u32 smem_u32(const void* p) {
    u32 a;
    asm("{ .reg .u64 t; cvta.to.shared.u64 t, %1; cvt.u32.u64 %0, t; }" : "=r"(a) : "l"(p));
    return a;
}
__device__ __forceinline__ void ldm4(u32* r, u32 addr) {
    asm volatile("ldmatrix.sync.aligned.m8n8.x4.shared.b16 {%0,%1,%2,%3}, [%4];"
                 : "=r"(r[0]), "=r"(r[1]), "=r"(r[2]), "=r"(r[3]) : "r"(addr));
}
__device__ __forceinline__ void ldm4t(u32* r, u32 addr) {
    asm volatile("ldmatrix.sync.aligned.m8n8.x4.trans.shared.b16 {%0,%1,%2,%3}, [%4];"
                 : "=r"(r[0]), "=r"(r[1]), "=r"(r[2]), "=r"(r[3]) : "r"(addr));
}
__device__ __forceinline__ void mma_bf16(float* d, const u32* a, u32 b0, u32 b1) {
    asm volatile("mma.sync.aligned.m16n8k16.row.col.f32.bf16.bf16.f32 "
                 "{%0,%1,%2,%3}, {%4,%5,%6,%7}, {%8,%9}, {%0,%1,%2,%3};"
                 : "+f"(d[0]), "+f"(d[1]), "+f"(d[2]), "+f"(d[3])
                 : "r"(a[0]), "r"(a[1]), "r"(a[2]), "r"(a[3]), "r"(b0), "r"(b1));
}
__device__ __forceinline__ void bsplit(float v, u16& h, u16& l) {
    __nv_bfloat16 hb = __float2bfloat16(v);
    h = __bfloat16_as_ushort(hb);
    l = __bfloat16_as_ushort(__float2bfloat16(v - __bfloat162float(hb)));
}

// ---------------------------------------------------------------------------
// prep: one d per block (256 blocks x 128 threads). LUT rank-sort + scans,
// then 256-bucket pstart table (binary count over sorted breakpoints).
// ---------------------------------------------------------------------------
__global__ void kan_prep(const float* __restrict__ w1, const float* __restrict__ b1,
                         const float* __restrict__ w2, const float* __restrict__ b2)
{
    __shared__ float st[64], sS[64], sC[64];
    __shared__ float rs[2], rc[2], tws[1], twc[1];
    const int d = blockIdx.x, t = threadIdx.x, lane = t & 31;

    float key = 0.f, dS = 0.f, dC = 0.f, bS = 0.f, bC = 0.f;
    if (t < 64) {
        const float w = w1[(d << 6) + t];
        const float b = b1[(d << 6) + t];
        const float v = w2[(d << 6) + t];
        if (w == 0.f) {
            key = __int_as_float(0x7f800000);
            bC = fmaxf(b, 0.f) * v;
        } else {
            key = -b / w;
            const float pS = w * v, pC = b * v;
            if (w > 0.f) { dS = pS;  dC = pC; }
            else         { dS = -pS; dC = -pC; bS = pS; bC = pC; }
        }
        st[t] = key;
    }
    __syncthreads();
    int rank = 0;
    if (t < 64) {
        #pragma unroll
        for (int j = 0; j < 64; ++j) {
            const float tj = st[j];
            rank += (tj < key || (tj == key && j < t)) ? 1 : 0;
        }
    }
    __syncthreads();
    if (t < 64) {
        st[rank] = key; sS[rank] = dS; sC[rank] = dC;
        float rbS = bS, rbC = bC;
        #pragma unroll
        for (int off = 16; off >= 1; off >>= 1) {
            rbS += __shfl_xor_sync(~0u, rbS, off);
            rbC += __shfl_xor_sync(~0u, rbC, off);
        }
        if (lane == 0) { rs[t >> 5] = rbS; rc[t >> 5] = rbC; }
    }
    __syncthreads();
    float s = 0.f, c = 0.f;
    if (t < 64) {
        s = sS[t]; c = sC[t];
        #pragma unroll
        for (int off = 1; off < 32; off <<= 1) {
            const float vs = __shfl_up_sync(~0u, s, off);
            const float vc = __shfl_up_sync(~0u, c, off);
            if (lane >= off) { s += vs; c += vc; }
        }
        if (t == 31) { tws[0] = s; twc[0] = c; }
    }
    __syncthreads();
    if (t < 64) {
        if (t >= 32) { s += tws[0]; c += twc[0]; }
        const float baseS = rs[0] + rs[1];
        const float baseC = rc[0] + rc[1] + __ldg(b2 + d);
        g_lutT[(d << 6) + t] = st[t];
        if (t == 0) g_lutSC[d * 65] = make_float2(baseS, baseC);
        g_lutSC[d * 65 + 1 + t] = make_float2(baseS + s, baseC + c);
    }
    // bucket table: pstart[k] = #(t < e_k), e_k = k/16 - 8; pstart[0] = 0
    for (int k = t; k < 256; k += 128) {
        int p = 0;
        if (k > 0) {
            const float e = (float)k * 0.0625f - 8.0f;
            p += (st[31]     < e) ? 32 : 0;
            p += (st[p + 15] < e) ? 16 : 0;
            p += (st[p + 7]  < e) ? 8  : 0;
            p += (st[p + 3]  < e) ? 4  : 0;
            p += (st[p + 1]  < e) ? 2  : 0;
            p += (st[p]      < e) ? 1  : 0;
            if (p < 64 && st[p] < e) ++p;
        }
        g_pst[(d << 8) + k] = (u8)p;
    }
}

// ---------------------------------------------------------------------------
// eval: bucket-start + short walk, emit A as bf16 hi/lo u16 [d][b] directly.
// grid (B/128, D/64), 256 threads, occ 2. smem ~101KB.
// ---------------------------------------------------------------------------
__global__ __launch_bounds__(256, 2) void kan_eval(const float* __restrict__ x)
{
    extern __shared__ float sm[];
    float*  sT   = sm;                          // [64 d][72] (+inf sentinel pad)
    float2* sSC  = (float2*)(sm + 4608);        // [64 d][65]
    u8*     spst = (u8*)(sm + 12928);           // [64 d][256]
    float*  sx   = sm + 17024;                  // [64 d][129] transposed x tile

    const int b0 = blockIdx.x << 7;
    const int d0 = blockIdx.y << 6;
    const int t  = threadIdx.x;

    {
        const float4* gt = (const float4*)(g_lutT + (d0 << 6));
        const float4* gc = ((const float4*)g_lutSC) + (size_t)(d0 >> 6) * 2080;
        const uint4*  gp = (const uint4*)(g_pst + (d0 << 8));
        for (int k = t; k < 1024; k += 256) {
            const int dl = k >> 4, c = (k & 15) << 2;
            *(float4*)(sT + dl * 72 + c) = gt[k];
        }
        for (int k = t; k < 2080; k += 256) ((float4*)sSC)[k] = gc[k];
        for (int k = t; k < 1024; k += 256) ((uint4*)spst)[k] = gp[k];
        for (int k = t; k < 512; k += 256)
            sT[(k >> 3) * 72 + 64 + (k & 7)] = __int_as_float(0x7f800000);
    }
    for (int k = t; k < 2048; k += 256) {
        const int b = k >> 4, c = (k & 15) << 2;
        float4 v = *(const float4*)(x + (size_t)(b0 + b) * Dn + d0 + c);
        sx[(c + 0) * 129 + b] = v.x;
        sx[(c + 1) * 129 + b] = v.y;
        sx[(c + 2) * 129 + b] = v.z;
        sx[(c + 3) * 129 + b] = v.w;
    }
    __syncthreads();

    const int warp = t >> 5, lane = t & 31;
    #pragma unroll 1
    for (int j = 0; j < 8; ++j) {
        const int dl = (warp << 3) + j;
        const float*  tt = sT + dl * 72;
        const float2* sc = sSC + dl * 65;
        const u8*     pp = spst + (dl << 8);
        u16* oh = g_Ah16 + (size_t)(d0 + dl) * Bn + b0;
        u16* ol = g_Al16 + (size_t)(d0 + dl) * Bn + b0;
        #pragma unroll
        for (int c = 0; c < 4; ++c) {
            const int bl = lane + (c << 5);
            const float xv = sx[dl * 129 + bl];
            int idx = __float2int_rz((xv + 8.0f) * 16.0f);
            idx = max(0, min(idx, 255));
            int p = pp[idx];
            while (tt[p] <= xv) ++p;        // sentinel +inf terminates; p <= 64
            const float2 scv = sc[p];
            const float v = fmaf(scv.x, xv, scv.y);
            u16 h, l;
            bsplit(v, h, l);
            oh[bl] = h;
            ol[bl] = l;
        }
    }
}

// ---------------------------------------------------------------------------
// kan_mma: GEMM1 (K=256) -> in-register relu/bsplit -> GEMM2 (K=64).
// A loaded from [d][b] u16 via ldmatrix.x4.trans (regs reordered r0,r2,r1,r3).
// grid 128 (btile 64), 128 threads, ~211KB smem, occ 1.
// ---------------------------------------------------------------------------
#define OF_B1H 0
#define OF_B1L 33792
#define OF_AH  67584
#define OF_AL  104448
#define OF_B2H 141312
#define OF_B2L 178176
#define OF_SB1 215040
#define OF_SB2 215296
#define MMA_SMEM 216320
// pitches (bytes): B1 rows = 528; A rows = 144 (72 u16); B2 rows = 144

__global__ __launch_bounds__(128, 1) void kan_mma(
    const float* __restrict__ wo1, const float* __restrict__ bo1,
    const float* __restrict__ wo2, const float* __restrict__ bo2,
    float* __restrict__ out)
{
    extern __shared__ char smc[];
    const u32 sb = smem_u32(smc);
    const int t = threadIdx.x;
    const int b0 = blockIdx.x << 6;

    // ---- wo1 [64][256] -> bf16 hi/lo (pitch 264 u16)
    for (int idx = t; idx < 4096; idx += 128) {
        const int n = idx >> 6, k4 = (idx & 63) << 2;
        const float4 v = *(const float4*)(wo1 + (n << 8) + k4);
        u16 h[4], l[4];
        bsplit(v.x, h[0], l[0]); bsplit(v.y, h[1], l[1]);
        bsplit(v.z, h[2], l[2]); bsplit(v.w, h[3], l[3]);
        *(ushort4*)(smc + OF_B1H + n * 528 + (k4 << 1)) = make_ushort4(h[0], h[1], h[2], h[3]);
        *(ushort4*)(smc + OF_B1L + n * 528 + (k4 << 1)) = make_ushort4(l[0], l[1], l[2], l[3]);
    }
    // ---- wo2 [256][64] -> bf16 hi/lo (pitch 72 u16)
    for (int idx = t; idx < 4096; idx += 128) {
        const int o = idx >> 4, i4 = (idx & 15) << 2;
        const float4 v = *(const float4*)(wo2 + (o << 6) + i4);
        u16 h[4], l[4];
        bsplit(v.x, h[0], l[0]); bsplit(v.y, h[1], l[1]);
        bsplit(v.z, h[2], l[2]); bsplit(v.w, h[3], l[3]);
        *(ushort4*)(smc + OF_B2H + o * 144 + (i4 << 1)) = make_ushort4(h[0], h[1], h[2], h[3]);
        *(ushort4*)(smc + OF_B2L + o * 144 + (i4 << 1)) = make_ushort4(l[0], l[1], l[2], l[3]);
    }
    // ---- A tile [256 d][64 b] u16 (pitch 72 u16 = 144B, conflict-free ldmatrix)
    for (int idx = t; idx < 2048; idx += 128) {
        const int r = idx >> 3, c = idx & 7;
        *(uint4*)(smc + OF_AH + r * 144 + (c << 4)) =
            *(const uint4*)(g_Ah16 + (size_t)r * Bn + b0 + (c << 3));
        *(uint4*)(smc + OF_AL + r * 144 + (c << 4)) =
            *(const uint4*)(g_Al16 + (size_t)r * Bn + b0 + (c << 3));
    }
    {
        float* sb1 = (float*)(smc + OF_SB1);
        float* sb2 = (float*)(smc + OF_SB2);
        if (t < 64) sb1[t] = __ldg(bo1 + t);
        sb2[t] = __ldg(bo2 + t);
        sb2[t + 128] = __ldg(bo2 + t + 128);
    }
    __syncthreads();

    const int w = t >> 5, lane = t & 31;
    const int m0 = w << 4;
    const int q = lane >> 3, rr = lane & 7;
    const int tq = lane & 3, gg = lane >> 2;

    const int b_rowq = (q >> 1) << 3;
    const int b_colq = (q & 1) << 3;

    // A trans-ldmatrix address: row = kt*16 + (q&1)*8 + rr (d), col = m0 + (q>>1)*8 (b)
    const u32 aAh = sb + OF_AH + (((q & 1) << 3) + rr) * 144 + ((m0 + ((q >> 1) << 3)) << 1);
    const u32 aAl = aAh + (OF_AL - OF_AH);

    // ---- GEMM1: D1[8 ntiles][4], K=256 (16 k-steps), hh + lh + hl fused
    float D1[8][4];
    #pragma unroll
    for (int nt = 0; nt < 8; ++nt)
        #pragma unroll
        for (int r = 0; r < 4; ++r) D1[nt][r] = 0.f;

    #pragma unroll 4
    for (int kt = 0; kt < 16; ++kt) {
        u32 ah[4], al[4], tmp;
        ldm4t(ah, aAh + kt * 2304);
        ldm4t(al, aAl + kt * 2304);
        tmp = ah[1]; ah[1] = ah[2]; ah[2] = tmp;   // trans quadrants -> a-frag order
        tmp = al[1]; al[1] = al[2]; al[2] = tmp;
        #pragma unroll
        for (int np = 0; np < 4; ++np) {
            const int brow = (np << 4) + rr + b_rowq;
            u32 bh[4], bl[4];
            ldm4(bh, sb + OF_B1H + brow * 528 + (kt << 5) + (b_colq << 1));
            ldm4(bl, sb + OF_B1L + brow * 528 + (kt << 5) + (b_colq << 1));
            mma_bf16(D1[2 * np],     ah, bh[0], bh[1]);
            mma_bf16(D1[2 * np],     al, bh[0], bh[1]);
            mma_bf16(D1[2 * np],     ah, bl[0], bl[1]);
            mma_bf16(D1[2 * np + 1], ah, bh[2], bh[3]);
            mma_bf16(D1[2 * np + 1], al, bh[2], bh[3]);
            mma_bf16(D1[2 * np + 1], ah, bl[2], bl[3]);
        }
    }

    // ---- epilogue 1: relu(D1 + bo1) -> A2 fragments (hi/lo) in registers
    u32 a2h[4][4], a2l[4][4];
    {
        const float* sb1 = (const float*)(smc + OF_SB1);
        #pragma unroll
        for (int nt = 0; nt < 8; ++nt) {
            const float bv0 = sb1[(nt << 3) + (tq << 1)];
            const float bv1 = sb1[(nt << 3) + (tq << 1) + 1];
            const float v0 = fmaxf(D1[nt][0] + bv0, 0.f);
            const float v1 = fmaxf(D1[nt][1] + bv1, 0.f);
            const float v2 = fmaxf(D1[nt][2] + bv0, 0.f);
            const float v3 = fmaxf(D1[nt][3] + bv1, 0.f);
            u16 h0, l0, h1, l1, h2, l2, h3, l3;
            bsplit(v0, h0, l0); bsplit(v1, h1, l1);
            bsplit(v2, h2, l2); bsplit(v3, h3, l3);
            const int j = nt >> 1;
            const int o = (nt & 1) << 1;
            a2h[j][o]     = (u32)h0 | ((u32)h1 << 16);
            a2h[j][o + 1] = (u32)h2 | ((u32)h3 << 16);
            a2l[j][o]     = (u32)l0 | ((u32)l1 << 16);
            a2l[j][o + 1] = (u32)l2 | ((u32)l3 << 16);
        }
    }

    // ---- GEMM2: out = g @ wo2^T + bo2, K=64 (4 k-steps), N=256 in 2 halves
    const float* sb2 = (const float*)(smc + OF_SB2);
    #pragma unroll 1
    for (int half = 0; half < 2; ++half) {
        float D2[16][4];
        #pragma unroll
        for (int nt = 0; nt < 16; ++nt)
            #pragma unroll
            for (int r = 0; r < 4; ++r) D2[nt][r] = 0.f;

        #pragma unroll
        for (int j = 0; j < 4; ++j) {
            #pragma unroll
            for (int p2 = 0; p2 < 8; ++p2) {
                const int brow = (half << 7) + (p2 << 4) + rr + b_rowq;
                u32 bh[4], bl[4];
                ldm4(bh, sb + OF_B2H + brow * 144 + (j << 5) + (b_colq << 1));
                ldm4(bl, sb + OF_B2L + brow * 144 + (j << 5) + (b_colq << 1));
                mma_bf16(D2[2 * p2],     a2h[j], bh[0], bh[1]);
                mma_bf16(D2[2 * p2],     a2l[j], bh[0], bh[1]);
                mma_bf16(D2[2 * p2],     a2h[j], bl[0], bl[1]);
                mma_bf16(D2[2 * p2 + 1], a2h[j], bh[2], bh[3]);
                mma_bf16(D2[2 * p2 + 1], a2l[j], bh[2], bh[3]);
                mma_bf16(D2[2 * p2 + 1], a2h[j], bl[2], bl[3]);
            }
        }
        #pragma unroll
        for (int nt = 0; nt < 16; ++nt) {
            const int ob = (half << 7) + (nt << 3);
            const float bv0 = sb2[ob + (tq << 1)];
            const float bv1 = sb2[ob + (tq << 1) + 1];
            const int row = b0 + m0 + gg;
            *(float2*)(out + (size_t)row * ONn + ob + (tq << 1)) =
                make_float2(D2[nt][0] + bv0, D2[nt][1] + bv1);
            *(float2*)(out + (size_t)(row + 8) * ONn + ob + (tq << 1)) =
                make_float2(D2[nt][2] + bv0, D2[nt][3] + bv1);
        }
    }
}

// ---------------------------------------------------------------------------
extern "C" void kernel_launch(void* const* d_in, const int* in_sizes, int n_in,
                              void* d_out, int out_size)
{
    const float* x   = (const float*)d_in[0];
    const float* w1  = (const float*)d_in[1];
    const float* b1  = (const float*)d_in[2];
    const float* w2  = (const float*)d_in[3];
    const float* b2  = (const float*)d_in[4];
    const float* wo1 = (const float*)d_in[5];
    const float* bo1 = (const float*)d_in[6];
    const float* wo2 = (const float*)d_in[7];
    const float* bo2 = (const float*)d_in[8];
    float* out = (float*)d_out;

    const int evalsm = 25280 * 4;                    // 101120
    cudaFuncSetAttribute(kan_eval, cudaFuncAttributeMaxDynamicSharedMemorySize, evalsm);
    cudaFuncSetAttribute(kan_mma,  cudaFuncAttributeMaxDynamicSharedMemorySize, MMA_SMEM);

    kan_prep<<<Dn, 128>>>(w1, b1, w2, b2);
    kan_eval<<<dim3(Bn / 128, Dn / 64), 256, evalsm>>>(x);
    kan_mma<<<Bn / 64, 128, MMA_SMEM>>>(wo1, bo1, wo2, bo2, out);
}

// round 11
// speedup vs baseline: 1.1232x; 1.1232x over previous
#include <cuda_runtime.h>
#include <cuda_bf16.h>
#include <cstdint>

#define Bn 8192
#define Dn 256
#define INn 64
#define ONn 256

typedef unsigned int u32;
typedef unsigned short u16;

// A matrix (inner acts) as packed bf16 pairs: [b][d/2], low half = even d
__device__ __align__(16) u32 g_Ah[(size_t)Bn * (Dn / 2)];   // 4MB
__device__ __align__(16) u32 g_Al[(size_t)Bn * (Dn / 2)];   // 4MB
__device__ float g_lutT[Dn * INn];
__device__ __align__(16) float2 g_lutSC[Dn * (INn + 1)];

__device__ __forceinline__ u32 smem_u32(const void* p) {
    u32 a;
    asm("{ .reg .u64 t; cvta.to.shared.u64 t, %1; cvt.u32.u64 %0, t; }" : "=r"(a) : "l"(p));
    return a;
}
__device__ __forceinline__ void ldm4(u32* r, u32 addr) {
    asm volatile("ldmatrix.sync.aligned.m8n8.x4.shared.b16 {%0,%1,%2,%3}, [%4];"
                 : "=r"(r[0]), "=r"(r[1]), "=r"(r[2]), "=r"(r[3]) : "r"(addr));
}
__device__ __forceinline__ void mma_bf16(float* d, const u32* a, u32 b0, u32 b1) {
    asm volatile("mma.sync.aligned.m16n8k16.row.col.f32.bf16.bf16.f32 "
                 "{%0,%1,%2,%3}, {%4,%5,%6,%7}, {%8,%9}, {%0,%1,%2,%3};"
                 : "+f"(d[0]), "+f"(d[1]), "+f"(d[2]), "+f"(d[3])
                 : "r"(a[0]), "r"(a[1]), "r"(a[2]), "r"(a[3]), "r"(b0), "r"(b1));
}
__device__ __forceinline__ void bsplit(float v, u16& h, u16& l) {
    __nv_bfloat16 hb = __float2bfloat16(v);
    h = __bfloat16_as_ushort(hb);
    l = __bfloat16_as_ushort(__float2bfloat16(v - __bfloat162float(hb)));
}

// ---------------------------------------------------------------------------
// prep: PWL LUT, 4 d per block (rank-sort, no serial chains). grid 64 x 256.
// (identical to round-9 version, which measured 5.15us)
// ---------------------------------------------------------------------------
__global__ void kan_prep(const float* __restrict__ w1, const float* __restrict__ b1,
                         const float* __restrict__ w2, const float* __restrict__ b2)
{
    __shared__ float st[4][64], sS[4][64], sC[4][64];
    __shared__ float rs[4][2], rc[4][2], tws[4][2], twc[4][2];
    const int t = threadIdx.x;
    const int g = t >> 6, i = t & 63, lane = t & 31, half = (t >> 5) & 1;
    const int d = (blockIdx.x << 2) + g;

    const float w = w1[(d << 6) + i];
    const float b = b1[(d << 6) + i];
    const float v = w2[(d << 6) + i];
    float key, dS, dC, bS = 0.f, bC = 0.f;
    if (w == 0.f) {
        key = __int_as_float(0x7f800000); dS = 0.f; dC = 0.f;
        bC = fmaxf(b, 0.f) * v;
    } else {
        key = -b / w;
        const float pS = w * v, pC = b * v;
        if (w > 0.f) { dS = pS;  dC = pC; }
        else         { dS = -pS; dC = -pC; bS = pS; bC = pC; }
    }
    st[g][i] = key;
    __syncthreads();
    int rank = 0;
    #pragma unroll
    for (int j = 0; j < 64; ++j) {
        const float tj = st[g][j];
        rank += (tj < key || (tj == key && j < i)) ? 1 : 0;
    }
    __syncthreads();
    st[g][rank] = key; sS[g][rank] = dS; sC[g][rank] = dC;
    float rbS = bS, rbC = bC;
    #pragma unroll
    for (int off = 16; off >= 1; off >>= 1) {
        rbS += __shfl_xor_sync(~0u, rbS, off);
        rbC += __shfl_xor_sync(~0u, rbC, off);
    }
    if (lane == 0) { rs[g][half] = rbS; rc[g][half] = rbC; }
    __syncthreads();
    float s = sS[g][i], c = sC[g][i];
    #pragma unroll
    for (int off = 1; off < 32; off <<= 1) {
        const float vs = __shfl_up_sync(~0u, s, off);
        const float vc = __shfl_up_sync(~0u, c, off);
        if (lane >= off) { s += vs; c += vc; }
    }
    if (lane == 31) { tws[g][half] = s; twc[g][half] = c; }
    __syncthreads();
    if (half) { s += tws[g][0]; c += twc[g][0]; }
    const float baseS = rs[g][0] + rs[g][1];
    const float baseC = rc[g][0] + rc[g][1] + __ldg(b2 + d);
    g_lutT[(d << 6) + i] = st[g][i];
    if (i == 0) g_lutSC[d * 65] = make_float2(baseS, baseC);
    g_lutSC[d * 65 + 1 + i] = make_float2(baseS + s, baseC + c);
}

// ---------------------------------------------------------------------------
// eval: PWL evaluate + emit A as packed bf16 hi/lo [b][d] (identical to R9)
// ---------------------------------------------------------------------------
__global__ __launch_bounds__(256, 2) void kan_eval(const float* __restrict__ x)
{
    extern __shared__ float sm[];
    float*  sT  = sm;                        // [64 d][64]
    float2* sSC = (float2*)(sm + 4096);      // [64 d][65]
    float*  sx  = sm + 4096 + 8320;          // [64 d][129]; later staging u32[128][64]

    const int b0 = blockIdx.x << 7;
    const int d0 = blockIdx.y << 6;
    const int t  = threadIdx.x;

    {
        const float4* gt = (const float4*)(g_lutT + (d0 << 6));
        const float4* gc = ((const float4*)g_lutSC) + (size_t)(d0 >> 6) * 2080;
        for (int k = t; k < 1024; k += 256) ((float4*)sT)[k] = gt[k];
        for (int k = t; k < 2080; k += 256) ((float4*)sSC)[k] = gc[k];
    }
    for (int k = t; k < 2048; k += 256) {
        const int b = k >> 4, c = (k & 15) << 2;
        float4 v = *(const float4*)(x + (size_t)(b0 + b) * Dn + d0 + c);
        sx[(c + 0) * 129 + b] = v.x;
        sx[(c + 1) * 129 + b] = v.y;
        sx[(c + 2) * 129 + b] = v.z;
        sx[(c + 3) * 129 + b] = v.w;
    }
    __syncthreads();

    const int warp = t >> 5, lane = t & 31;
    float val[8][4];
    #pragma unroll
    for (int j = 0; j < 8; ++j) {
        const int dl = (warp << 3) + j;
        const float*  tt = sT + (dl << 6);
        const float2* sc = sSC + dl * 65;
        #pragma unroll
        for (int c = 0; c < 4; ++c) {
            const float xv = sx[dl * 129 + lane + (c << 5)];
            int p = 0;
            p += (tt[31]     <= xv) ? 32 : 0;
            p += (tt[p + 15] <= xv) ? 16 : 0;
            p += (tt[p + 7]  <= xv) ? 8  : 0;
            p += (tt[p + 3]  <= xv) ? 4  : 0;
            p += (tt[p + 1]  <= xv) ? 2  : 0;
            p += (tt[p]      <= xv) ? 1  : 0;
            p += (tt[p]      <= xv) ? 1  : 0;
            const float2 scv = sc[p];
            val[j][c] = fmaf(scv.x, xv, scv.y);
        }
    }
    __syncthreads();   // all sx reads complete; reuse region as staging

    u32* su = (u32*)sx;  // [128 b][64 dl], col XOR (b & 31)
    #pragma unroll
    for (int j = 0; j < 8; ++j) {
        const int dl = (warp << 3) + j;
        #pragma unroll
        for (int c = 0; c < 4; ++c) {
            const int bl = lane + (c << 5);
            u16 h, l;
            bsplit(val[j][c], h, l);
            su[(bl << 6) + (dl ^ (bl & 31))] = ((u32)h << 16) | l;
        }
    }
    __syncthreads();

    const int d0h = d0 >> 1;
    for (int idx = t; idx < 4096; idx += 256) {
        const int row = idx >> 5, p = idx & 31, f = row & 31;
        const u32 e0 = su[(row << 6) + (((p << 1))     ^ f)];
        const u32 e1 = su[(row << 6) + (((p << 1) | 1) ^ f)];
        const u32 hi = (e0 >> 16) | (e1 & 0xFFFF0000u);
        const u32 lo = (e0 & 0xFFFFu) | (e1 << 16);
        g_Ah[(size_t)(b0 + row) * 128 + d0h + p] = hi;
        g_Al[(size_t)(b0 + row) * 128 + d0h + p] = lo;
    }
}

// ---------------------------------------------------------------------------
// kan_mma v2: 256 threads (8 warps). GEMM1: 4 m-warps x 2 n-warps (192 mma
// each, chain distance 4). g exchanged via smem carved from dead B1 region.
// GEMM2: n128 per warp-half. Addressing identical to R9-verified patterns.
// ---------------------------------------------------------------------------
#define OF_B1H 0
#define OF_B1L 33792
#define OF_AH  67584
#define OF_AL  101376
#define OF_B2H 135168
#define OF_B2L 172032
#define OF_SB1 208896
#define OF_SB2 209152
#define MMA_SMEM 210176
#define OF_GH 0          // g hi: reuses B1H region after GEMM1 (+sync)
#define OF_GL 9216       // g lo: 64 rows x 144B each
// pitches (bytes): A,B1 rows = 528 (264 bf16); B2,g rows = 144 (72 bf16)

__global__ __launch_bounds__(256, 1) void kan_mma(
    const float* __restrict__ wo1, const float* __restrict__ bo1,
    const float* __restrict__ wo2, const float* __restrict__ bo2,
    float* __restrict__ out)
{
    extern __shared__ char smc[];
    const u32 sb = smem_u32(smc);
    const int t = threadIdx.x;
    const int b0 = blockIdx.x << 6;

    // ---- wo1 [64][256] -> bf16 hi/lo (pitch 264 u16)
    for (int idx = t; idx < 4096; idx += 256) {
        const int n = idx >> 6, k4 = (idx & 63) << 2;
        const float4 v = *(const float4*)(wo1 + (n << 8) + k4);
        u16 h[4], l[4];
        bsplit(v.x, h[0], l[0]); bsplit(v.y, h[1], l[1]);
        bsplit(v.z, h[2], l[2]); bsplit(v.w, h[3], l[3]);
        *(ushort4*)(smc + OF_B1H + n * 528 + (k4 << 1)) = make_ushort4(h[0], h[1], h[2], h[3]);
        *(ushort4*)(smc + OF_B1L + n * 528 + (k4 << 1)) = make_ushort4(l[0], l[1], l[2], l[3]);
    }
    // ---- wo2 [256][64] -> bf16 hi/lo (pitch 72 u16)
    for (int idx = t; idx < 4096; idx += 256) {
        const int o = idx >> 4, i4 = (idx & 15) << 2;
        const float4 v = *(const float4*)(wo2 + (o << 6) + i4);
        u16 h[4], l[4];
        bsplit(v.x, h[0], l[0]); bsplit(v.y, h[1], l[1]);
        bsplit(v.z, h[2], l[2]); bsplit(v.w, h[3], l[3]);
        *(ushort4*)(smc + OF_B2H + o * 144 + (i4 << 1)) = make_ushort4(h[0], h[1], h[2], h[3]);
        *(ushort4*)(smc + OF_B2L + o * 144 + (i4 << 1)) = make_ushort4(l[0], l[1], l[2], l[3]);
    }
    // ---- A tile rows b0..b0+63 (bf16-packed) -> sAh/sAl (pitch 264 u16)
    for (int idx = t; idx < 2048; idx += 256) {
        const int b = idx >> 5, c4 = (idx & 31) << 2;
        *(uint4*)(smc + OF_AH + b * 528 + (c4 << 2)) =
            *(const uint4*)(g_Ah + (size_t)(b0 + b) * 128 + c4);
        *(uint4*)(smc + OF_AL + b * 528 + (c4 << 2)) =
            *(const uint4*)(g_Al + (size_t)(b0 + b) * 128 + c4);
    }
    {
        float* sb1 = (float*)(smc + OF_SB1);
        float* sb2 = (float*)(smc + OF_SB2);
        if (t < 64) sb1[t] = __ldg(bo1 + t);
        if (t < 128) {
            sb2[t] = __ldg(bo2 + t);
            sb2[t + 128] = __ldg(bo2 + t + 128);
        }
    }
    __syncthreads();

    const int w = t >> 5, lane = t & 31;
    const int mrow = (w & 3) << 4;      // 4 m-warps
    const int nh = w >> 2;              // 2 n-halves
    const int q = lane >> 3, rr = lane & 7;
    const int tq = lane & 3, gg = lane >> 2;
    const int b_rowq = (q >> 1) << 3;
    const int b_colq = (q & 1) << 3;

    const u32 aAh = sb + OF_AH + (mrow + rr + ((q & 1) << 3)) * 528 + (((q >> 1) << 3) << 1);
    const u32 aAl = aAh + (OF_AL - OF_AH);

    // ---- GEMM1: D1[4 ntiles][4], warp covers m16 x n32 (np0, np0+1)
    float D1[4][4];
    #pragma unroll
    for (int nt = 0; nt < 4; ++nt)
        #pragma unroll
        for (int r = 0; r < 4; ++r) D1[nt][r] = 0.f;

    const int np0 = nh << 1;
    #pragma unroll 4
    for (int kt = 0; kt < 16; ++kt) {
        u32 ah[4], al[4];
        ldm4(ah, aAh + (kt << 5));
        ldm4(al, aAl + (kt << 5));
        const u32 bb = sb + OF_B1H + (kt << 5) + (b_colq << 1);
        const int r0 = (np0 << 4) + rr + b_rowq;
        u32 bh0[4], bh1[4], bl0[4], bl1[4];
        ldm4(bh0, bb + r0 * 528);
        ldm4(bh1, bb + (r0 + 16) * 528);
        ldm4(bl0, bb + 33792 + r0 * 528);
        ldm4(bl1, bb + 33792 + (r0 + 16) * 528);
        // 12 mma, round-robin across 4 accumulators (RAW distance 4)
        mma_bf16(D1[0], ah, bh0[0], bh0[1]);
        mma_bf16(D1[1], ah, bh0[2], bh0[3]);
        mma_bf16(D1[2], ah, bh1[0], bh1[1]);
        mma_bf16(D1[3], ah, bh1[2], bh1[3]);
        mma_bf16(D1[0], al, bh0[0], bh0[1]);
        mma_bf16(D1[1], al, bh0[2], bh0[3]);
        mma_bf16(D1[2], al, bh1[0], bh1[1]);
        mma_bf16(D1[3], al, bh1[2], bh1[3]);
        mma_bf16(D1[0], ah, bl0[0], bl0[1]);
        mma_bf16(D1[1], ah, bl0[2], bl0[3]);
        mma_bf16(D1[2], ah, bl1[0], bl1[1]);
        mma_bf16(D1[3], ah, bl1[2], bl1[3]);
    }

    // ---- epilogue 1: relu(D1 + bo1) -> packed g words (registers)
    u32 ghw[4][2], glw[4][2];
    {
        const float* sb1f = (const float*)(smc + OF_SB1);
        #pragma unroll
        for (int nt = 0; nt < 4; ++nt) {
            const int col = (nh << 5) + (nt << 3) + (tq << 1);
            const float bv0 = sb1f[col], bv1 = sb1f[col + 1];
            const float v0 = fmaxf(D1[nt][0] + bv0, 0.f);
            const float v1 = fmaxf(D1[nt][1] + bv1, 0.f);
            const float v2 = fmaxf(D1[nt][2] + bv0, 0.f);
            const float v3 = fmaxf(D1[nt][3] + bv1, 0.f);
            u16 h0, l0, h1, l1, h2, l2, h3, l3;
            bsplit(v0, h0, l0); bsplit(v1, h1, l1);
            bsplit(v2, h2, l2); bsplit(v3, h3, l3);
            ghw[nt][0] = (u32)h0 | ((u32)h1 << 16);
            ghw[nt][1] = (u32)h2 | ((u32)h3 << 16);
            glw[nt][0] = (u32)l0 | ((u32)l1 << 16);
            glw[nt][1] = (u32)l2 | ((u32)l3 << 16);
        }
    }
    __syncthreads();   // all GEMM1 B1 reads done -> safe to overwrite with g

    #pragma unroll
    for (int nt = 0; nt < 4; ++nt) {
        const int c2 = ((nh << 5) + (nt << 3) + (tq << 1)) << 1;
        *(u32*)(smc + OF_GH + (mrow + gg) * 144 + c2)     = ghw[nt][0];
        *(u32*)(smc + OF_GH + (mrow + gg + 8) * 144 + c2) = ghw[nt][1];
        *(u32*)(smc + OF_GL + (mrow + gg) * 144 + c2)     = glw[nt][0];
        *(u32*)(smc + OF_GL + (mrow + gg + 8) * 144 + c2) = glw[nt][1];
    }
    __syncthreads();

    // ---- GEMM2: D2[16 ntiles][4], warp covers m16 x n128, K=64
    float D2[16][4];
    #pragma unroll
    for (int nt = 0; nt < 16; ++nt)
        #pragma unroll
        for (int r = 0; r < 4; ++r) D2[nt][r] = 0.f;

    const u32 gA = sb + OF_GH + (mrow + rr + ((q & 1) << 3)) * 144;
    #pragma unroll
    for (int j = 0; j < 4; ++j) {
        u32 a2h[4], a2l[4];
        const u32 ga = gA + (((j << 4) + ((q >> 1) << 3)) << 1);
        ldm4(a2h, ga);
        ldm4(a2l, ga + (OF_GL - OF_GH));
        #pragma unroll
        for (int pp = 0; pp < 4; ++pp) {
            const int p2 = pp << 1;
            const u32 bb = sb + OF_B2H + (j << 5) + (b_colq << 1);
            const int r0 = (nh << 7) + (p2 << 4) + rr + b_rowq;
            u32 bh0[4], bh1[4], bl0[4], bl1[4];
            ldm4(bh0, bb + r0 * 144);
            ldm4(bh1, bb + (r0 + 16) * 144);
            ldm4(bl0, bb + 36864 + r0 * 144);
            ldm4(bl1, bb + 36864 + (r0 + 16) * 144);
            float* d0 = D2[(p2 << 1) + 0];
            float* d1 = D2[(p2 << 1) + 1];
            float* d2 = D2[(p2 << 1) + 2];
            float* d3 = D2[(p2 << 1) + 3];
            mma_bf16(d0, a2h, bh0[0], bh0[1]);
            mma_bf16(d1, a2h, bh0[2], bh0[3]);
            mma_bf16(d2, a2h, bh1[0], bh1[1]);
            mma_bf16(d3, a2h, bh1[2], bh1[3]);
            mma_bf16(d0, a2l, bh0[0], bh0[1]);
            mma_bf16(d1, a2l, bh0[2], bh0[3]);
            mma_bf16(d2, a2l, bh1[0], bh1[1]);
            mma_bf16(d3, a2l, bh1[2], bh1[3]);
            mma_bf16(d0, a2h, bl0[0], bl0[1]);
            mma_bf16(d1, a2h, bl0[2], bl0[3]);
            mma_bf16(d2, a2h, bl1[0], bl1[1]);
            mma_bf16(d3, a2h, bl1[2], bl1[3]);
        }
    }

    // ---- store out + bo2
    {
        const float* sb2f = (const float*)(smc + OF_SB2);
        #pragma unroll
        for (int nt = 0; nt < 16; ++nt) {
            const int ob = (nh << 7) + (nt << 3);
            const float bv0 = sb2f[ob + (tq << 1)];
            const float bv1 = sb2f[ob + (tq << 1) + 1];
            const int row = b0 + mrow + gg;
            *(float2*)(out + (size_t)row * ONn + ob + (tq << 1)) =
                make_float2(D2[nt][0] + bv0, D2[nt][1] + bv1);
            *(float2*)(out + (size_t)(row + 8) * ONn + ob + (tq << 1)) =
                make_float2(D2[nt][2] + bv0, D2[nt][3] + bv1);
        }
    }
}

// ---------------------------------------------------------------------------
extern "C" void kernel_launch(void* const* d_in, const int* in_sizes, int n_in,
                              void* d_out, int out_size)
{
    const float* x   = (const float*)d_in[0];
    const float* w1  = (const float*)d_in[1];
    const float* b1  = (const float*)d_in[2];
    const float* w2  = (const float*)d_in[3];
    const float* b2  = (const float*)d_in[4];
    const float* wo1 = (const float*)d_in[5];
    const float* bo1 = (const float*)d_in[6];
    const float* wo2 = (const float*)d_in[7];
    const float* bo2 = (const float*)d_in[8];
    float* out = (float*)d_out;

    const int evalsm = (4096 + 8320 + 8256) * 4;     // 82688
    cudaFuncSetAttribute(kan_eval, cudaFuncAttributeMaxDynamicSharedMemorySize, evalsm);
    cudaFuncSetAttribute(kan_mma,  cudaFuncAttributeMaxDynamicSharedMemorySize, MMA_SMEM);

    kan_prep<<<64, 256>>>(w1, b1, w2, b2);
    kan_eval<<<dim3(Bn / 128, Dn / 64), 256, evalsm>>>(x);
    kan_mma<<<Bn / 64, 256, MMA_SMEM>>>(wo1, bo1, wo2, bo2, out);
}